// round 11
// baseline (speedup 1.0000x reference)
#include <cuda_runtime.h>
#include <math.h>
#include <cstdint>

// Problem constants
#define Bq   2
#define Hq   8
#define Nq   2048
#define Mq   2048
#define DIMq 512
#define DHq  64
#define INNERq 512   // Hq*DHq

// Device scratch (no cudaMalloc allowed)
__device__ float g_Q[Bq * Hq * Nq * DHq];      // [b,h,n,d] tf32-rounded
__device__ float g_K[Bq * Hq * Mq * DHq];      // [b,h,m,d] tf32-rounded
__device__ float g_V[Bq * Hq * Nq * DHq];      // [b,h,m,d] tf32-rounded
__device__ float g_O[Bq * Nq * INNERq];        // [b,n,h*d] tf32-rounded
// Pre-rounded (tf32) copies of inputs
__device__ float c_x  [Bq * Nq * DIMq];
__device__ float c_x1 [Bq * Mq * DIMq];
__device__ float c_wqv[DIMq * 2 * INNERq];
__device__ float c_wk [DIMq * INNERq];
__device__ float c_wo [INNERq * DIMq];

// ---------------------------------------------------------------------------
__device__ __forceinline__ float tf32r(float x) {
    unsigned u;
    asm("cvt.rna.tf32.f32 %0, %1;" : "=r"(u) : "f"(x));
    return __uint_as_float(u);
}
#define FU(x) __float_as_uint(x)

__device__ __forceinline__ void mma8(float& c0, float& c1, float& c2, float& c3,
                                     unsigned a0, unsigned a1, unsigned a2, unsigned a3,
                                     unsigned b0, unsigned b1) {
    asm volatile(
        "mma.sync.aligned.m16n8k8.row.col.f32.tf32.tf32.f32 "
        "{%0,%1,%2,%3}, {%4,%5,%6,%7}, {%8,%9}, {%0,%1,%2,%3};\n"
        : "+f"(c0), "+f"(c1), "+f"(c2), "+f"(c3)
        : "r"(a0), "r"(a1), "r"(a2), "r"(a3), "r"(b0), "r"(b1));
}

__device__ __forceinline__ void cp16(unsigned dst, const void* src) {
    asm volatile("cp.async.cg.shared.global [%0], [%1], 16;\n" :: "r"(dst), "l"(src));
}
#define CP_COMMIT() asm volatile("cp.async.commit_group;\n")
#define CP_WAIT0()  asm volatile("cp.async.wait_group 0;\n")
#define CP_WAIT1()  asm volatile("cp.async.wait_group 1;\n")

// ---------------------------------------------------------------------------
// Kernel 0: pre-round inputs to tf32
// ---------------------------------------------------------------------------
#define F4_X   (Bq * Nq * DIMq / 4)
#define F4_X1  (Bq * Mq * DIMq / 4)
#define F4_WQV (DIMq * 2 * INNERq / 4)
#define F4_WK  (DIMq * INNERq / 4)
#define F4_WO  (INNERq * DIMq / 4)
#define F4_TOT (F4_X + F4_X1 + F4_WQV + F4_WK + F4_WO)

__global__ void __launch_bounds__(256) prep_kernel(const float* __restrict__ x,
                                                   const float* __restrict__ x1,
                                                   const float* __restrict__ wqv,
                                                   const float* __restrict__ wk,
                                                   const float* __restrict__ wo) {
    int i = blockIdx.x * 256 + threadIdx.x;
    if (i >= F4_TOT) return;
    const float* src; float* dst; int off;
    if (i < F4_X)                       { src = x;   dst = c_x;   off = i; }
    else if (i < F4_X + F4_X1)          { src = x1;  dst = c_x1;  off = i - F4_X; }
    else if (i < F4_X + F4_X1 + F4_WQV) { src = wqv; dst = c_wqv; off = i - F4_X - F4_X1; }
    else if (i < F4_TOT - F4_WO)        { src = wk;  dst = c_wk;  off = i - F4_X - F4_X1 - F4_WQV; }
    else                                { src = wo;  dst = c_wo;  off = i - (F4_TOT - F4_WO); }
    float4 v = *(const float4*)&src[4 * (size_t)off];
    v.x = tf32r(v.x); v.y = tf32r(v.y); v.z = tf32r(v.z); v.w = tf32r(v.w);
    *(float4*)&dst[4 * (size_t)off] = v;
}

// ---------------------------------------------------------------------------
// 128x128 tf32 GEMM core (mma.sync), cp.async 2-stage
// ---------------------------------------------------------------------------
#define ASZ (128 * 20)
#define BSZ (16 * 136)

__device__ __forceinline__ void gemm128_pipe(const float* __restrict__ A, int lda,
                                             const float* __restrict__ B, int ldb,
                                             int row0, int col0, int K,
                                             float c[16][4],
                                             float* sA, float* sB) {
    const int tid  = threadIdx.x;
    const int lane = tid & 31;
    const int w    = tid >> 5;
    const int wm   = w >> 2;
    const int wn   = w & 3;
    const int g    = lane >> 2;
    const int t    = lane & 3;

    const unsigned aB = (unsigned)__cvta_generic_to_shared(sA);
    const unsigned bB = (unsigned)__cvta_generic_to_shared(sB);

    auto issue = [&](int ko, int st) {
        const float* Ag = A + (size_t)row0 * lda + ko;
#pragma unroll
        for (int i = 0; i < 2; i++) {
            int ff = tid + i * 256;
            int r = ff >> 2, c4 = (ff & 3) * 4;
            cp16(aB + (st * ASZ + r * 20 + c4) * 4, Ag + (size_t)r * lda + c4);
        }
        const float* Bg = B + (size_t)ko * ldb + col0;
#pragma unroll
        for (int i = 0; i < 2; i++) {
            int ff = tid + i * 256;
            int r = ff >> 5, c4 = (ff & 31) * 4;
            cp16(bB + (st * BSZ + r * 136 + c4) * 4, Bg + (size_t)r * ldb + c4);
        }
        CP_COMMIT();
    };

    const int nIter = K / 16;
    issue(0, 0);

    for (int it = 0; it < nIter; it++) {
        __syncthreads();
        if (it + 1 < nIter) { issue((it + 1) * 16, (it + 1) & 1); CP_WAIT1(); }
        else                { CP_WAIT0(); }
        __syncthreads();

        const float* cA = sA + (it & 1) * ASZ;
        const float* cB = sB + (it & 1) * BSZ;

#pragma unroll
        for (int kk = 0; kk < 16; kk += 8) {
            unsigned a[4][4], b[4][2];
#pragma unroll
            for (int mt = 0; mt < 4; mt++) {
                int rl = (wm * 64 + mt * 16 + g) * 20;
                int rh = rl + 8 * 20;
                a[mt][0] = FU(cA[rl + kk + t]);
                a[mt][1] = FU(cA[rh + kk + t]);
                a[mt][2] = FU(cA[rl + kk + t + 4]);
                a[mt][3] = FU(cA[rh + kk + t + 4]);
            }
#pragma unroll
            for (int nt = 0; nt < 4; nt++) {
                int cc = wn * 32 + nt * 8 + g;
                b[nt][0] = FU(cB[(kk + t) * 136 + cc]);
                b[nt][1] = FU(cB[(kk + t + 4) * 136 + cc]);
            }
#pragma unroll
            for (int mt = 0; mt < 4; mt++)
#pragma unroll
                for (int nt = 0; nt < 4; nt++)
                    mma8(c[mt * 4 + nt][0], c[mt * 4 + nt][1],
                         c[mt * 4 + nt][2], c[mt * 4 + nt][3],
                         a[mt][0], a[mt][1], a[mt][2], a[mt][3],
                         b[nt][0], b[nt][1]);
        }
    }
}

// ---------------------------------------------------------------------------
// Kernel 1: merged projections (blocks [0,256): QV; [256,384): K)
// ---------------------------------------------------------------------------
__global__ void __launch_bounds__(256, 2) proj_kernel() {
    __shared__ float sA[2 * ASZ];
    __shared__ float sB[2 * BSZ];
    float c[16][4] = {};

    const int bid = blockIdx.x;
    const bool isQV = (bid < 256);
    int row0, col0;
    if (isQV) { col0 = (bid & 7) * 128;         row0 = (bid >> 3) * 128; }
    else      { col0 = ((bid - 256) & 3) * 128; row0 = ((bid - 256) >> 2) * 128; }

    if (isQV) gemm128_pipe(c_x,  DIMq, c_wqv, 2 * INNERq, row0, col0, DIMq, c, sA, sB);
    else      gemm128_pipe(c_x1, DIMq, c_wk,  INNERq,     row0, col0, DIMq, c, sA, sB);

    const int tid  = threadIdx.x;
    const int lane = tid & 31;
    const int w    = tid >> 5;
    const int wm   = w >> 2, wn = w & 3;
    const int g    = lane >> 2, t = lane & 3;

#pragma unroll
    for (int mt = 0; mt < 4; mt++) {
#pragma unroll
        for (int nt = 0; nt < 4; nt++) {
            int r  = row0 + wm * 64 + mt * 16 + g;
            int cc = col0 + wn * 32 + nt * 8 + 2 * t;
            int b  = r >> 11, n = r & 2047;
            float* dst;
            int colq;
            if (isQV) {
                bool isV = (cc >= INNERq);
                dst  = isV ? g_V : g_Q;
                colq = isV ? cc - INNERq : cc;
            } else {
                dst  = g_K;
                colq = cc;
            }
            int h = colq >> 6, d = colq & 63;
            size_t base = (((size_t)(b * Hq + h)) * Nq + n) * DHq + d;
            float* p = &c[mt * 4 + nt][0];
            *(float2*)&dst[base]           = make_float2(tf32r(p[0]), tf32r(p[1]));
            *(float2*)&dst[base + 8 * DHq] = make_float2(tf32r(p[2]), tf32r(p[3]));
        }
    }
}

// ---------------------------------------------------------------------------
// Kernel 2: flash attention, tf32 mma.sync, 4 warps x 32 Q rows (block = 128
// rows). Q in dedicated smem (fragments re-read per chunk); P separate; bias
// cp.async double-buffered. Per warp per chunk: 256 MMAs vs ~420 LDS-cyc ->
// MMA-bound. K/V L2 traffic halved vs 64-row blocks.
// Smem floats: Qs@0 (128x68) | Ps@8704 (128x68) | Ks@17408 (2 x 64x68)
//              | Vs@26112 (2 x 64x72) | Bs@35328 (2 x 128x68)
// ---------------------------------------------------------------------------
#define OFF_P  8704
#define OFF_K  17408
#define OFF_V  26112
#define OFF_B  35328
#define KSTG   4352   // 64*68
#define VSTG   4608   // 64*72
#define BSTG   8704   // 128*68
#define ATTN_SMEM_BYTES ((OFF_B + 2 * BSTG) * 4)   // 210,944 B

__global__ void __launch_bounds__(128) attn_kernel(const float* __restrict__ attn_mat,
                                                   const float* __restrict__ dots_para,
                                                   const float* __restrict__ mat_para) {
    extern __shared__ float sm[];
    const int tid  = threadIdx.x;
    const int lane = tid & 31;
    const int w    = tid >> 5;
    const int g    = lane >> 2;
    const int t    = lane & 3;
    const int b    = blockIdx.z;
    const int h    = blockIdx.y;
    const int n0   = blockIdx.x * 128;
    const size_t bh = (size_t)(b * Hq + h);

    const float dp = __ldg(dots_para) * 0.125f;
    const float mp = __ldg(mat_para);

    const unsigned smB = (unsigned)__cvta_generic_to_shared(sm);

    // Issue K/V/bias for chunk ch into stage st
    auto issue = [&](int ch, int st) {
        const int m0 = ch * 64;
        const float* Kg = g_K + (bh * Mq + m0) * DHq;
        const float* Vg = g_V + (bh * Mq + m0) * DHq;
#pragma unroll
        for (int i = 0; i < 8; i++) {
            int idx = tid + i * 128;
            int r = idx >> 4, c4 = (idx & 15) * 4;
            cp16(smB + (OFF_K + st * KSTG + r * 68 + c4) * 4, Kg + r * 64 + c4);
            cp16(smB + (OFF_V + st * VSTG + r * 72 + c4) * 4, Vg + r * 64 + c4);
        }
        const float* Ag = attn_mat + (bh * Nq + n0) * (size_t)Mq + m0;
#pragma unroll
        for (int i = 0; i < 16; i++) {
            int idx = tid + i * 128;
            int r = idx >> 4, c4 = (idx & 15) * 4;
            cp16(smB + (OFF_B + st * BSTG + r * 68 + c4) * 4, Ag + (size_t)r * Mq + c4);
        }
        CP_COMMIT();
    };

    // Prologue: Q (128x64) + chunk 0
    {
        const float* Qg = g_Q + (bh * Nq + n0) * DHq;
#pragma unroll
        for (int i = 0; i < 16; i++) {
            int idx = tid + i * 128;
            int r = idx >> 4, c4 = (idx & 15) * 4;
            cp16(smB + (r * 68 + c4) * 4, Qg + r * 64 + c4);
        }
        issue(0, 0);
        CP_WAIT0();
        __syncthreads();
    }

    float o[2][8][4] = {};      // per-warp 32 rows x 64 d
    float rs[2][2] = {};        // row-sums: [mt][lo/hi]
    const int row0 = w * 32 + g;

    for (int ch = 0; ch < 32; ch++) {
        const int pb = ch & 1;
        __syncthreads();    // prev chunk's reads of stage pb^1 complete
        if (ch + 1 < 32) { issue(ch + 1, pb ^ 1); CP_WAIT1(); }
        else             { CP_WAIT0(); }
        __syncthreads();    // stage pb visible

        const float* Kb = sm + OFF_K + pb * KSTG;
        const float* Vb = sm + OFF_V + pb * VSTG;
        const float* Bb = sm + OFF_B + pb * BSTG;

        // ---- S = Q K^T : 2 m16 tiles x 8 n8 tiles x 8 k8 steps ----
        float s[2][8][4] = {};
#pragma unroll
        for (int k8 = 0; k8 < 8; k8++) {
            unsigned qa[2][4];
#pragma unroll
            for (int mt = 0; mt < 2; mt++) {
                int rl = (row0 + mt * 16) * 68;
                int rh = rl + 8 * 68;
                qa[mt][0] = FU(sm[rl + k8 * 8 + t]);
                qa[mt][1] = FU(sm[rh + k8 * 8 + t]);
                qa[mt][2] = FU(sm[rl + k8 * 8 + t + 4]);
                qa[mt][3] = FU(sm[rh + k8 * 8 + t + 4]);
            }
#pragma unroll
            for (int nt = 0; nt < 8; nt++) {
                int cb = (nt * 8 + g) * 68 + k8 * 8 + t;
                unsigned b0 = FU(Kb[cb]);
                unsigned b1 = FU(Kb[cb + 4]);
                mma8(s[0][nt][0], s[0][nt][1], s[0][nt][2], s[0][nt][3],
                     qa[0][0], qa[0][1], qa[0][2], qa[0][3], b0, b1);
                mma8(s[1][nt][0], s[1][nt][1], s[1][nt][2], s[1][nt][3],
                     qa[1][0], qa[1][1], qa[1][2], qa[1][3], b0, b1);
            }
        }

        // ---- bias + exp (no max; logits bounded), store P (tf32) ----
#pragma unroll
        for (int mt = 0; mt < 2; mt++) {
            int rl  = (row0 + mt * 16) * 68;
            int rh  = rl + 8 * 68;
#pragma unroll
            for (int nt = 0; nt < 8; nt++) {
                float2 blo = *(const float2*)&Bb[rl + nt * 8 + 2 * t];
                float2 bhi = *(const float2*)&Bb[rh + nt * 8 + 2 * t];
                float e0 = __expf(fmaf(s[mt][nt][0], dp, mp * blo.x));
                float e1 = __expf(fmaf(s[mt][nt][1], dp, mp * blo.y));
                float e2 = __expf(fmaf(s[mt][nt][2], dp, mp * bhi.x));
                float e3 = __expf(fmaf(s[mt][nt][3], dp, mp * bhi.y));
                rs[mt][0] += e0 + e1;
                rs[mt][1] += e2 + e3;
                *(float2*)&sm[OFF_P + rl + nt * 8 + 2 * t] =
                    make_float2(tf32r(e0), tf32r(e1));
                *(float2*)&sm[OFF_P + rh + nt * 8 + 2 * t] =
                    make_float2(tf32r(e2), tf32r(e3));
            }
        }
        __syncwarp();   // P rows are warp-private

        // ---- O += P @ V ----
#pragma unroll
        for (int k8 = 0; k8 < 8; k8++) {
            unsigned pa[2][4];
#pragma unroll
            for (int mt = 0; mt < 2; mt++) {
                int prl = OFF_P + (row0 + mt * 16) * 68;
                int prh = prl + 8 * 68;
                pa[mt][0] = FU(sm[prl + k8 * 8 + t]);
                pa[mt][1] = FU(sm[prh + k8 * 8 + t]);
                pa[mt][2] = FU(sm[prl + k8 * 8 + t + 4]);
                pa[mt][3] = FU(sm[prh + k8 * 8 + t + 4]);
            }
#pragma unroll
            for (int nt = 0; nt < 8; nt++) {
                int vb = (k8 * 8 + t) * 72 + nt * 8 + g;
                unsigned b0 = FU(Vb[vb]);
                unsigned b1 = FU(Vb[vb + 4 * 72]);
                mma8(o[0][nt][0], o[0][nt][1], o[0][nt][2], o[0][nt][3],
                     pa[0][0], pa[0][1], pa[0][2], pa[0][3], b0, b1);
                mma8(o[1][nt][0], o[1][nt][1], o[1][nt][2], o[1][nt][3],
                     pa[1][0], pa[1][1], pa[1][2], pa[1][3], b0, b1);
            }
        }
    }

    // ---- Epilogue: reduce row-sums across t lanes, normalize, store ----
#pragma unroll
    for (int mt = 0; mt < 2; mt++) {
        rs[mt][0] += __shfl_xor_sync(0xffffffffu, rs[mt][0], 1);
        rs[mt][0] += __shfl_xor_sync(0xffffffffu, rs[mt][0], 2);
        rs[mt][1] += __shfl_xor_sync(0xffffffffu, rs[mt][1], 1);
        rs[mt][1] += __shfl_xor_sync(0xffffffffu, rs[mt][1], 2);
        float inv0 = 1.0f / rs[mt][0];
        float inv1 = 1.0f / rs[mt][1];
        float* Og = g_O + ((size_t)b * Nq + n0 + row0 + mt * 16) * INNERq + h * DHq;
#pragma unroll
        for (int nt = 0; nt < 8; nt++) {
            *(float2*)&Og[nt * 8 + 2 * t] =
                make_float2(tf32r(o[mt][nt][0] * inv0), tf32r(o[mt][nt][1] * inv0));
            *(float2*)&Og[(size_t)8 * INNERq + nt * 8 + 2 * t] =
                make_float2(tf32r(o[mt][nt][2] * inv1), tf32r(o[mt][nt][3] * inv1));
        }
    }
}

// ---------------------------------------------------------------------------
// Kernel 3: output projection
// ---------------------------------------------------------------------------
__global__ void __launch_bounds__(256, 2) out_proj_kernel(const float* __restrict__ bout,
                                                          float* __restrict__ out) {
    __shared__ float sA[2 * ASZ];
    __shared__ float sB[2 * BSZ];
    float c[16][4] = {};
    const int row0 = blockIdx.y * 128;
    const int col0 = blockIdx.x * 128;
    gemm128_pipe(g_O, INNERq, c_wo, DIMq, row0, col0, INNERq, c, sA, sB);

    const int tid  = threadIdx.x;
    const int lane = tid & 31;
    const int w    = tid >> 5;
    const int wm   = w >> 2, wn = w & 3;
    const int g    = lane >> 2, t = lane & 3;

#pragma unroll
    for (int mt = 0; mt < 4; mt++) {
#pragma unroll
        for (int nt = 0; nt < 4; nt++) {
            int r  = row0 + wm * 64 + mt * 16 + g;
            int cc = col0 + wn * 32 + nt * 8 + 2 * t;
            float2 bb = *(const float2*)&bout[cc];
            *(float2*)&out[(size_t)r * DIMq + cc] =
                make_float2(c[mt * 4 + nt][0] + bb.x, c[mt * 4 + nt][1] + bb.y);
            *(float2*)&out[(size_t)(r + 8) * DIMq + cc] =
                make_float2(c[mt * 4 + nt][2] + bb.x, c[mt * 4 + nt][3] + bb.y);
        }
    }
}

// ---------------------------------------------------------------------------
extern "C" void kernel_launch(void* const* d_in, const int* in_sizes, int n_in,
                              void* d_out, int out_size) {
    const float* x    = (const float*)d_in[0];
    const float* x1   = (const float*)d_in[1];
    const float* am   = (const float*)d_in[2];
    const float* dp   = (const float*)d_in[3];
    const float* mp   = (const float*)d_in[4];
    const float* Wqv  = (const float*)d_in[5];
    const float* Wk   = (const float*)d_in[6];
    const float* Wout = (const float*)d_in[7];
    const float* bout = (const float*)d_in[8];
    float* out = (float*)d_out;

    cudaFuncSetAttribute(attn_kernel, cudaFuncAttributeMaxDynamicSharedMemorySize,
                         ATTN_SMEM_BYTES);

    prep_kernel<<<(F4_TOT + 255) / 256, 256>>>(x, x1, Wqv, Wk, Wout);
    proj_kernel<<<384, 256>>>();
    attn_kernel<<<dim3(Nq / 128, Hq, Bq), 128, ATTN_SMEM_BYTES>>>(am, dp, mp);
    out_proj_kernel<<<dim3(DIMq / 128, 4096 / 128), 256>>>(bout, out);
}

// round 12
// speedup vs baseline: 1.1382x; 1.1382x over previous
#include <cuda_runtime.h>
#include <math.h>
#include <cstdint>

// Problem constants
#define Bq   2
#define Hq   8
#define Nq   2048
#define Mq   2048
#define DIMq 512
#define DHq  64
#define INNERq 512   // Hq*DHq

// Device scratch (no cudaMalloc allowed)
__device__ float g_Q[Bq * Hq * Nq * DHq];      // [b,h,n,d] tf32-rounded
__device__ float g_K[Bq * Hq * Mq * DHq];      // [b,h,m,d] tf32-rounded
__device__ float g_V[Bq * Hq * Nq * DHq];      // [b,h,m,d] tf32-rounded
__device__ float g_O[Bq * Nq * INNERq];        // [b,n,h*d] tf32-rounded
// Pre-rounded (tf32) copies of inputs
__device__ float c_x  [Bq * Nq * DIMq];
__device__ float c_x1 [Bq * Mq * DIMq];
__device__ float c_wqv[DIMq * 2 * INNERq];
__device__ float c_wk [DIMq * INNERq];
__device__ float c_wo [INNERq * DIMq];

// ---------------------------------------------------------------------------
__device__ __forceinline__ float tf32r(float x) {
    unsigned u;
    asm("cvt.rna.tf32.f32 %0, %1;" : "=r"(u) : "f"(x));
    return __uint_as_float(u);
}
#define FU(x) __float_as_uint(x)

__device__ __forceinline__ void mma8(float& c0, float& c1, float& c2, float& c3,
                                     unsigned a0, unsigned a1, unsigned a2, unsigned a3,
                                     unsigned b0, unsigned b1) {
    asm volatile(
        "mma.sync.aligned.m16n8k8.row.col.f32.tf32.tf32.f32 "
        "{%0,%1,%2,%3}, {%4,%5,%6,%7}, {%8,%9}, {%0,%1,%2,%3};\n"
        : "+f"(c0), "+f"(c1), "+f"(c2), "+f"(c3)
        : "r"(a0), "r"(a1), "r"(a2), "r"(a3), "r"(b0), "r"(b1));
}

__device__ __forceinline__ void cp16(unsigned dst, const void* src) {
    asm volatile("cp.async.cg.shared.global [%0], [%1], 16;\n" :: "r"(dst), "l"(src));
}
#define CP_COMMIT() asm volatile("cp.async.commit_group;\n")
#define CP_WAIT0()  asm volatile("cp.async.wait_group 0;\n")
#define CP_WAIT1()  asm volatile("cp.async.wait_group 1;\n")

// ---------------------------------------------------------------------------
// Kernel 0: pre-round inputs to tf32
// ---------------------------------------------------------------------------
#define F4_X   (Bq * Nq * DIMq / 4)
#define F4_X1  (Bq * Mq * DIMq / 4)
#define F4_WQV (DIMq * 2 * INNERq / 4)
#define F4_WK  (DIMq * INNERq / 4)
#define F4_WO  (INNERq * DIMq / 4)
#define F4_TOT (F4_X + F4_X1 + F4_WQV + F4_WK + F4_WO)

__global__ void __launch_bounds__(256) prep_kernel(const float* __restrict__ x,
                                                   const float* __restrict__ x1,
                                                   const float* __restrict__ wqv,
                                                   const float* __restrict__ wk,
                                                   const float* __restrict__ wo) {
    int i = blockIdx.x * 256 + threadIdx.x;
    if (i >= F4_TOT) return;
    const float* src; float* dst; int off;
    if (i < F4_X)                       { src = x;   dst = c_x;   off = i; }
    else if (i < F4_X + F4_X1)          { src = x1;  dst = c_x1;  off = i - F4_X; }
    else if (i < F4_X + F4_X1 + F4_WQV) { src = wqv; dst = c_wqv; off = i - F4_X - F4_X1; }
    else if (i < F4_TOT - F4_WO)        { src = wk;  dst = c_wk;  off = i - F4_X - F4_X1 - F4_WQV; }
    else                                { src = wo;  dst = c_wo;  off = i - (F4_TOT - F4_WO); }
    float4 v = *(const float4*)&src[4 * (size_t)off];
    v.x = tf32r(v.x); v.y = tf32r(v.y); v.z = tf32r(v.z); v.w = tf32r(v.w);
    *(float4*)&dst[4 * (size_t)off] = v;
}

// ---------------------------------------------------------------------------
// 128x128 tf32 GEMM core (mma.sync), cp.async 2-stage
// ---------------------------------------------------------------------------
#define ASZ (128 * 20)
#define BSZ (16 * 136)

__device__ __forceinline__ void gemm128_pipe(const float* __restrict__ A, int lda,
                                             const float* __restrict__ B, int ldb,
                                             int row0, int col0, int K,
                                             float c[16][4],
                                             float* sA, float* sB) {
    const int tid  = threadIdx.x;
    const int lane = tid & 31;
    const int w    = tid >> 5;
    const int wm   = w >> 2;
    const int wn   = w & 3;
    const int g    = lane >> 2;
    const int t    = lane & 3;

    const unsigned aB = (unsigned)__cvta_generic_to_shared(sA);
    const unsigned bB = (unsigned)__cvta_generic_to_shared(sB);

    auto issue = [&](int ko, int st) {
        const float* Ag = A + (size_t)row0 * lda + ko;
#pragma unroll
        for (int i = 0; i < 2; i++) {
            int ff = tid + i * 256;
            int r = ff >> 2, c4 = (ff & 3) * 4;
            cp16(aB + (st * ASZ + r * 20 + c4) * 4, Ag + (size_t)r * lda + c4);
        }
        const float* Bg = B + (size_t)ko * ldb + col0;
#pragma unroll
        for (int i = 0; i < 2; i++) {
            int ff = tid + i * 256;
            int r = ff >> 5, c4 = (ff & 31) * 4;
            cp16(bB + (st * BSZ + r * 136 + c4) * 4, Bg + (size_t)r * ldb + c4);
        }
        CP_COMMIT();
    };

    const int nIter = K / 16;
    issue(0, 0);

    for (int it = 0; it < nIter; it++) {
        __syncthreads();
        if (it + 1 < nIter) { issue((it + 1) * 16, (it + 1) & 1); CP_WAIT1(); }
        else                { CP_WAIT0(); }
        __syncthreads();

        const float* cA = sA + (it & 1) * ASZ;
        const float* cB = sB + (it & 1) * BSZ;

#pragma unroll
        for (int kk = 0; kk < 16; kk += 8) {
            unsigned a[4][4], b[4][2];
#pragma unroll
            for (int mt = 0; mt < 4; mt++) {
                int rl = (wm * 64 + mt * 16 + g) * 20;
                int rh = rl + 8 * 20;
                a[mt][0] = FU(cA[rl + kk + t]);
                a[mt][1] = FU(cA[rh + kk + t]);
                a[mt][2] = FU(cA[rl + kk + t + 4]);
                a[mt][3] = FU(cA[rh + kk + t + 4]);
            }
#pragma unroll
            for (int nt = 0; nt < 4; nt++) {
                int cc = wn * 32 + nt * 8 + g;
                b[nt][0] = FU(cB[(kk + t) * 136 + cc]);
                b[nt][1] = FU(cB[(kk + t + 4) * 136 + cc]);
            }
#pragma unroll
            for (int mt = 0; mt < 4; mt++)
#pragma unroll
                for (int nt = 0; nt < 4; nt++)
                    mma8(c[mt * 4 + nt][0], c[mt * 4 + nt][1],
                         c[mt * 4 + nt][2], c[mt * 4 + nt][3],
                         a[mt][0], a[mt][1], a[mt][2], a[mt][3],
                         b[nt][0], b[nt][1]);
        }
    }
}

// ---------------------------------------------------------------------------
// Kernel 1: merged projections (blocks [0,256): QV; [256,384): K)
// ---------------------------------------------------------------------------
__global__ void __launch_bounds__(256, 2) proj_kernel() {
    __shared__ float sA[2 * ASZ];
    __shared__ float sB[2 * BSZ];
    float c[16][4] = {};

    const int bid = blockIdx.x;
    const bool isQV = (bid < 256);
    int row0, col0;
    if (isQV) { col0 = (bid & 7) * 128;         row0 = (bid >> 3) * 128; }
    else      { col0 = ((bid - 256) & 3) * 128; row0 = ((bid - 256) >> 2) * 128; }

    if (isQV) gemm128_pipe(c_x,  DIMq, c_wqv, 2 * INNERq, row0, col0, DIMq, c, sA, sB);
    else      gemm128_pipe(c_x1, DIMq, c_wk,  INNERq,     row0, col0, DIMq, c, sA, sB);

    const int tid  = threadIdx.x;
    const int lane = tid & 31;
    const int w    = tid >> 5;
    const int wm   = w >> 2, wn = w & 3;
    const int g    = lane >> 2, t = lane & 3;

#pragma unroll
    for (int mt = 0; mt < 4; mt++) {
#pragma unroll
        for (int nt = 0; nt < 4; nt++) {
            int r  = row0 + wm * 64 + mt * 16 + g;
            int cc = col0 + wn * 32 + nt * 8 + 2 * t;
            int b  = r >> 11, n = r & 2047;
            float* dst;
            int colq;
            if (isQV) {
                bool isV = (cc >= INNERq);
                dst  = isV ? g_V : g_Q;
                colq = isV ? cc - INNERq : cc;
            } else {
                dst  = g_K;
                colq = cc;
            }
            int h = colq >> 6, d = colq & 63;
            size_t base = (((size_t)(b * Hq + h)) * Nq + n) * DHq + d;
            float* p = &c[mt * 4 + nt][0];
            *(float2*)&dst[base]           = make_float2(tf32r(p[0]), tf32r(p[1]));
            *(float2*)&dst[base + 8 * DHq] = make_float2(tf32r(p[2]), tf32r(p[3]));
        }
    }
}

// ---------------------------------------------------------------------------
// Kernel 2: flash attention, tf32 mma.sync, deferred-PV pipeline.
// 64-row Q tiles, 4 warps x 16 rows, 2 blocks/SM (106.5KB smem).
// Body of chunk ch runs S(ch) and PV(ch-1) interleaved in one unrolled loop.
// Smem floats: P0@0, P1@4352 (64x68) | K0@8704, K1@13056 (64x68)
//              | V0@17408, V1@22016 (64x72).  Q staged in P0 (prologue only).
// ---------------------------------------------------------------------------
#define PS    4352            // 64*68
#define OFF_K 8704
#define KS    4352            // 64*68
#define OFF_V 17408
#define VS    4608            // 64*72
#define ATTN_SMEM_BYTES ((OFF_V + 2 * VS) * 4)   // 106,496 B

__global__ void __launch_bounds__(128, 2) attn_kernel(const float* __restrict__ attn_mat,
                                                      const float* __restrict__ dots_para,
                                                      const float* __restrict__ mat_para) {
    extern __shared__ float sm[];
    const int tid  = threadIdx.x;
    const int lane = tid & 31;
    const int w    = tid >> 5;
    const int g    = lane >> 2;
    const int t    = lane & 3;
    const int b    = blockIdx.z;
    const int h    = blockIdx.y;
    const int n0   = blockIdx.x * 64;
    const size_t bh = (size_t)(b * Hq + h);

    const float dp = __ldg(dots_para) * 0.125f;
    const float mp = __ldg(mat_para);

    const unsigned smB = (unsigned)__cvta_generic_to_shared(sm);

    // Loaders: K stride 68, V stride 72 (both conflict-free for fragment reads)
    auto ldK = [&](int ch) {     // K(ch) -> K[ch&1]
        const float* Kg = g_K + (bh * Mq + ch * 64) * DHq;
        unsigned dst = smB + (OFF_K + (ch & 1) * KS) * 4;
#pragma unroll
        for (int i = 0; i < 8; i++) {
            int idx = tid + i * 128;
            int r = idx >> 4, c4 = (idx & 15) * 4;
            cp16(dst + (r * 68 + c4) * 4, Kg + r * 64 + c4);
        }
    };
    auto ldV = [&](int ch) {     // V(ch) -> V[ch&1]
        const float* Vg = g_V + (bh * Mq + ch * 64) * DHq;
        unsigned dst = smB + (OFF_V + (ch & 1) * VS) * 4;
#pragma unroll
        for (int i = 0; i < 8; i++) {
            int idx = tid + i * 128;
            int r = idx >> 4, c4 = (idx & 15) * 4;
            cp16(dst + (r * 72 + c4) * 4, Vg + r * 64 + c4);
        }
    };

    // Prologue: Q -> P0 staging, K(0), V(0)
    {
        const float* Qg = g_Q + (bh * Nq + n0) * DHq;
#pragma unroll
        for (int i = 0; i < 8; i++) {
            int idx = tid + i * 128;
            int r = idx >> 4, c4 = (idx & 15) * 4;
            cp16(smB + (r * 68 + c4) * 4, Qg + r * 64 + c4);
        }
        ldK(0);
        CP_COMMIT();
        ldV(0);
        CP_COMMIT();
        CP_WAIT0();
        __syncthreads();
    }

    // Q fragments (warp-private rows w*16+g, +8) from staging
    const int rl = (w * 16 + g) * 68;
    const int rh = rl + 8 * 68;
    unsigned qa[8][4];
#pragma unroll
    for (int k8 = 0; k8 < 8; k8++) {
        qa[k8][0] = FU(sm[rl + k8 * 8 + t]);
        qa[k8][1] = FU(sm[rh + k8 * 8 + t]);
        qa[k8][2] = FU(sm[rl + k8 * 8 + t + 4]);
        qa[k8][3] = FU(sm[rh + k8 * 8 + t + 4]);
    }

    const float* AmBase = attn_mat + (bh * Nq + (n0 + w * 16 + g)) * (size_t)Mq;
    float o[8][4] = {};
    float rs0 = 0.0f, rs1 = 0.0f;

    // helper macro bodies written inline below to keep register use tight
    // ---- Peeled chunk 0: S(0) + exp + store P(0) ----
    {
        ldK(1); CP_COMMIT();
        const float* Am = AmBase + 0;
        float2 alo[8], ahi[8];
#pragma unroll
        for (int nt = 0; nt < 8; nt++) {
            alo[nt] = __ldg((const float2*)&Am[nt * 8 + 2 * t]);
            ahi[nt] = __ldg((const float2*)&Am[(size_t)8 * Mq + nt * 8 + 2 * t]);
        }
        const float* Kb = sm + OFF_K;       // K[0]
        float s[8][4] = {};
#pragma unroll
        for (int k8 = 0; k8 < 8; k8++) {
#pragma unroll
            for (int nt = 0; nt < 8; nt++) {
                int cb = (nt * 8 + g) * 68 + k8 * 8 + t;
                mma8(s[nt][0], s[nt][1], s[nt][2], s[nt][3],
                     qa[k8][0], qa[k8][1], qa[k8][2], qa[k8][3],
                     FU(Kb[cb]), FU(Kb[cb + 4]));
            }
        }
#pragma unroll
        for (int nt = 0; nt < 8; nt++) {
            float e0 = __expf(fmaf(s[nt][0], dp, mp * alo[nt].x));
            float e1 = __expf(fmaf(s[nt][1], dp, mp * alo[nt].y));
            float e2 = __expf(fmaf(s[nt][2], dp, mp * ahi[nt].x));
            float e3 = __expf(fmaf(s[nt][3], dp, mp * ahi[nt].y));
            rs0 += e0 + e1; rs1 += e2 + e3;
            *(float2*)&sm[rl + nt * 8 + 2 * t] = make_float2(tf32r(e0), tf32r(e1));
            *(float2*)&sm[rh + nt * 8 + 2 * t] = make_float2(tf32r(e2), tf32r(e3));
        }
        __syncthreads();
        ldV(1); CP_COMMIT();
    }

    // ---- Main loop: chunk ch does S(ch) + PV(ch-1) fused ----
    for (int ch = 1; ch < 32; ch++) {
        CP_WAIT1();          // K(ch) landed (V(ch) may still be in flight)
        __syncthreads();     // all warps done with K[(ch+1)&1] reads (S(ch-1))
        if (ch < 31) { ldK(ch + 1); CP_COMMIT(); }

        const float* Am = AmBase + ch * 64;
        float2 alo[8], ahi[8];
#pragma unroll
        for (int nt = 0; nt < 8; nt++) {
            alo[nt] = __ldg((const float2*)&Am[nt * 8 + 2 * t]);
            ahi[nt] = __ldg((const float2*)&Am[(size_t)8 * Mq + nt * 8 + 2 * t]);
        }

        const float* Kb = sm + OFF_K + (ch & 1) * KS;
        const float* Vb = sm + OFF_V + ((ch - 1) & 1) * VS;
        const float* Pp = sm + ((ch - 1) & 1) * PS;
        float* Pc = sm + (ch & 1) * PS;

        float s[8][4] = {};
#pragma unroll
        for (int k8 = 0; k8 < 8; k8++) {
            unsigned pa0 = FU(Pp[rl + k8 * 8 + t]);
            unsigned pa1 = FU(Pp[rh + k8 * 8 + t]);
            unsigned pa2 = FU(Pp[rl + k8 * 8 + t + 4]);
            unsigned pa3 = FU(Pp[rh + k8 * 8 + t + 4]);
#pragma unroll
            for (int nt = 0; nt < 8; nt++) {
                int cb = (nt * 8 + g) * 68 + k8 * 8 + t;
                mma8(s[nt][0], s[nt][1], s[nt][2], s[nt][3],
                     qa[k8][0], qa[k8][1], qa[k8][2], qa[k8][3],
                     FU(Kb[cb]), FU(Kb[cb + 4]));
                int vb = (k8 * 8 + t) * 72 + nt * 8 + g;
                mma8(o[nt][0], o[nt][1], o[nt][2], o[nt][3],
                     pa0, pa1, pa2, pa3,
                     FU(Vb[vb]), FU(Vb[vb + 4 * 72]));
            }
        }

        // softmax (no max; logits bounded) + store P(ch)
#pragma unroll
        for (int nt = 0; nt < 8; nt++) {
            float e0 = __expf(fmaf(s[nt][0], dp, mp * alo[nt].x));
            float e1 = __expf(fmaf(s[nt][1], dp, mp * alo[nt].y));
            float e2 = __expf(fmaf(s[nt][2], dp, mp * ahi[nt].x));
            float e3 = __expf(fmaf(s[nt][3], dp, mp * ahi[nt].y));
            rs0 += e0 + e1; rs1 += e2 + e3;
            *(float2*)&Pc[rl + nt * 8 + 2 * t] = make_float2(tf32r(e0), tf32r(e1));
            *(float2*)&Pc[rh + nt * 8 + 2 * t] = make_float2(tf32r(e2), tf32r(e3));
        }

        __syncthreads();     // all warps done reading V[(ch+1)&1] (PV(ch-1))
        if (ch < 31) { ldV(ch + 1); CP_COMMIT(); }
    }

    // ---- Final PV(31) ----
    CP_WAIT0();
    __syncthreads();
    {
        const float* Vb = sm + OFF_V + VS;   // V[1]
        const float* Pp = sm + PS;           // P[1]
#pragma unroll
        for (int k8 = 0; k8 < 8; k8++) {
            unsigned pa0 = FU(Pp[rl + k8 * 8 + t]);
            unsigned pa1 = FU(Pp[rh + k8 * 8 + t]);
            unsigned pa2 = FU(Pp[rl + k8 * 8 + t + 4]);
            unsigned pa3 = FU(Pp[rh + k8 * 8 + t + 4]);
#pragma unroll
            for (int nt = 0; nt < 8; nt++) {
                int vb = (k8 * 8 + t) * 72 + nt * 8 + g;
                mma8(o[nt][0], o[nt][1], o[nt][2], o[nt][3],
                     pa0, pa1, pa2, pa3,
                     FU(Vb[vb]), FU(Vb[vb + 4 * 72]));
            }
        }
    }

    // ---- Epilogue ----
    rs0 += __shfl_xor_sync(0xffffffffu, rs0, 1);
    rs0 += __shfl_xor_sync(0xffffffffu, rs0, 2);
    rs1 += __shfl_xor_sync(0xffffffffu, rs1, 1);
    rs1 += __shfl_xor_sync(0xffffffffu, rs1, 2);
    float inv0 = 1.0f / rs0, inv1 = 1.0f / rs1;

    float* Og = g_O + ((size_t)b * Nq + n0 + w * 16 + g) * INNERq + h * DHq;
#pragma unroll
    for (int nt = 0; nt < 8; nt++) {
        *(float2*)&Og[nt * 8 + 2 * t] =
            make_float2(tf32r(o[nt][0] * inv0), tf32r(o[nt][1] * inv0));
        *(float2*)&Og[(size_t)8 * INNERq + nt * 8 + 2 * t] =
            make_float2(tf32r(o[nt][2] * inv1), tf32r(o[nt][3] * inv1));
    }
}

// ---------------------------------------------------------------------------
// Kernel 3: output projection
// ---------------------------------------------------------------------------
__global__ void __launch_bounds__(256, 2) out_proj_kernel(const float* __restrict__ bout,
                                                          float* __restrict__ out) {
    __shared__ float sA[2 * ASZ];
    __shared__ float sB[2 * BSZ];
    float c[16][4] = {};
    const int row0 = blockIdx.y * 128;
    const int col0 = blockIdx.x * 128;
    gemm128_pipe(g_O, INNERq, c_wo, DIMq, row0, col0, INNERq, c, sA, sB);

    const int tid  = threadIdx.x;
    const int lane = tid & 31;
    const int w    = tid >> 5;
    const int wm   = w >> 2, wn = w & 3;
    const int g    = lane >> 2, t = lane & 3;

#pragma unroll
    for (int mt = 0; mt < 4; mt++) {
#pragma unroll
        for (int nt = 0; nt < 4; nt++) {
            int r  = row0 + wm * 64 + mt * 16 + g;
            int cc = col0 + wn * 32 + nt * 8 + 2 * t;
            float2 bb = *(const float2*)&bout[cc];
            *(float2*)&out[(size_t)r * DIMq + cc] =
                make_float2(c[mt * 4 + nt][0] + bb.x, c[mt * 4 + nt][1] + bb.y);
            *(float2*)&out[(size_t)(r + 8) * DIMq + cc] =
                make_float2(c[mt * 4 + nt][2] + bb.x, c[mt * 4 + nt][3] + bb.y);
        }
    }
}

// ---------------------------------------------------------------------------
extern "C" void kernel_launch(void* const* d_in, const int* in_sizes, int n_in,
                              void* d_out, int out_size) {
    const float* x    = (const float*)d_in[0];
    const float* x1   = (const float*)d_in[1];
    const float* am   = (const float*)d_in[2];
    const float* dp   = (const float*)d_in[3];
    const float* mp   = (const float*)d_in[4];
    const float* Wqv  = (const float*)d_in[5];
    const float* Wk   = (const float*)d_in[6];
    const float* Wout = (const float*)d_in[7];
    const float* bout = (const float*)d_in[8];
    float* out = (float*)d_out;

    cudaFuncSetAttribute(attn_kernel, cudaFuncAttributeMaxDynamicSharedMemorySize,
                         ATTN_SMEM_BYTES);

    prep_kernel<<<(F4_TOT + 255) / 256, 256>>>(x, x1, Wqv, Wk, Wout);
    proj_kernel<<<384, 256>>>();
    attn_kernel<<<dim3(Nq / 64, Hq, Bq), 128, ATTN_SMEM_BYTES>>>(am, dp, mp);
    out_proj_kernel<<<dim3(DIMq / 128, 4096 / 128), 256>>>(bout, out);
}

// round 13
// speedup vs baseline: 1.4352x; 1.2609x over previous
#include <cuda_runtime.h>
#include <cuda_fp16.h>
#include <math.h>
#include <cstdint>

// Problem constants
#define Bq   2
#define Hq   8
#define Nq   2048
#define Mq   2048
#define DIMq 512
#define DHq  64
#define INNERq 512   // Hq*DHq

// Device scratch (no cudaMalloc allowed)
__device__ __half g_Qh[Bq * Hq * Nq * DHq];    // [b,h,n,d] fp16
__device__ __half g_Kh[Bq * Hq * Mq * DHq];    // [b,h,m,d] fp16
__device__ __half g_Vt[Bq * Hq * DHq * Mq];    // [b,h,d,m] fp16 TRANSPOSED
__device__ float  g_O [Bq * Nq * INNERq];      // [b,n,h*d] tf32-rounded
// Pre-rounded (tf32) copies of projection inputs
__device__ float c_x  [Bq * Nq * DIMq];
__device__ float c_x1 [Bq * Mq * DIMq];
__device__ float c_wqv[DIMq * 2 * INNERq];
__device__ float c_wk [DIMq * INNERq];
__device__ float c_wo [INNERq * DIMq];

// ---------------------------------------------------------------------------
__device__ __forceinline__ float tf32r(float x) {
    unsigned u;
    asm("cvt.rna.tf32.f32 %0, %1;" : "=r"(u) : "f"(x));
    return __uint_as_float(u);
}
#define FU(x) __float_as_uint(x)

__device__ __forceinline__ void mma8(float& c0, float& c1, float& c2, float& c3,
                                     unsigned a0, unsigned a1, unsigned a2, unsigned a3,
                                     unsigned b0, unsigned b1) {
    asm volatile(
        "mma.sync.aligned.m16n8k8.row.col.f32.tf32.tf32.f32 "
        "{%0,%1,%2,%3}, {%4,%5,%6,%7}, {%8,%9}, {%0,%1,%2,%3};\n"
        : "+f"(c0), "+f"(c1), "+f"(c2), "+f"(c3)
        : "r"(a0), "r"(a1), "r"(a2), "r"(a3), "r"(b0), "r"(b1));
}

__device__ __forceinline__ void mma16(float& c0, float& c1, float& c2, float& c3,
                                      unsigned a0, unsigned a1, unsigned a2, unsigned a3,
                                      unsigned b0, unsigned b1) {
    asm volatile(
        "mma.sync.aligned.m16n8k16.row.col.f32.f16.f16.f32 "
        "{%0,%1,%2,%3}, {%4,%5,%6,%7}, {%8,%9}, {%0,%1,%2,%3};\n"
        : "+f"(c0), "+f"(c1), "+f"(c2), "+f"(c3)
        : "r"(a0), "r"(a1), "r"(a2), "r"(a3), "r"(b0), "r"(b1));
}

__device__ __forceinline__ void cp16(unsigned dst, const void* src) {
    asm volatile("cp.async.cg.shared.global [%0], [%1], 16;\n" :: "r"(dst), "l"(src));
}
#define CP_COMMIT() asm volatile("cp.async.commit_group;\n")
#define CP_WAIT0()  asm volatile("cp.async.wait_group 0;\n")
#define CP_WAIT1()  asm volatile("cp.async.wait_group 1;\n")

// ---------------------------------------------------------------------------
// Kernel 0: pre-round projection inputs to tf32
// ---------------------------------------------------------------------------
#define F4_X   (Bq * Nq * DIMq / 4)
#define F4_X1  (Bq * Mq * DIMq / 4)
#define F4_WQV (DIMq * 2 * INNERq / 4)
#define F4_WK  (DIMq * INNERq / 4)
#define F4_WO  (INNERq * DIMq / 4)
#define F4_TOT (F4_X + F4_X1 + F4_WQV + F4_WK + F4_WO)

__global__ void __launch_bounds__(256) prep_kernel(const float* __restrict__ x,
                                                   const float* __restrict__ x1,
                                                   const float* __restrict__ wqv,
                                                   const float* __restrict__ wk,
                                                   const float* __restrict__ wo) {
    int i = blockIdx.x * 256 + threadIdx.x;
    if (i >= F4_TOT) return;
    const float* src; float* dst; int off;
    if (i < F4_X)                       { src = x;   dst = c_x;   off = i; }
    else if (i < F4_X + F4_X1)          { src = x1;  dst = c_x1;  off = i - F4_X; }
    else if (i < F4_X + F4_X1 + F4_WQV) { src = wqv; dst = c_wqv; off = i - F4_X - F4_X1; }
    else if (i < F4_TOT - F4_WO)        { src = wk;  dst = c_wk;  off = i - F4_X - F4_X1 - F4_WQV; }
    else                                { src = wo;  dst = c_wo;  off = i - (F4_TOT - F4_WO); }
    float4 v = *(const float4*)&src[4 * (size_t)off];
    v.x = tf32r(v.x); v.y = tf32r(v.y); v.z = tf32r(v.z); v.w = tf32r(v.w);
    *(float4*)&dst[4 * (size_t)off] = v;
}

// ---------------------------------------------------------------------------
// 128x128 tf32 GEMM core (mma.sync), cp.async 2-stage
// ---------------------------------------------------------------------------
#define ASZ (128 * 20)
#define BSZ (16 * 136)

__device__ __forceinline__ void gemm128_pipe(const float* __restrict__ A, int lda,
                                             const float* __restrict__ B, int ldb,
                                             int row0, int col0, int K,
                                             float c[16][4],
                                             float* sA, float* sB) {
    const int tid  = threadIdx.x;
    const int lane = tid & 31;
    const int w    = tid >> 5;
    const int wm   = w >> 2;
    const int wn   = w & 3;
    const int g    = lane >> 2;
    const int t    = lane & 3;

    const unsigned aB = (unsigned)__cvta_generic_to_shared(sA);
    const unsigned bB = (unsigned)__cvta_generic_to_shared(sB);

    auto issue = [&](int ko, int st) {
        const float* Ag = A + (size_t)row0 * lda + ko;
#pragma unroll
        for (int i = 0; i < 2; i++) {
            int ff = tid + i * 256;
            int r = ff >> 2, c4 = (ff & 3) * 4;
            cp16(aB + (st * ASZ + r * 20 + c4) * 4, Ag + (size_t)r * lda + c4);
        }
        const float* Bg = B + (size_t)ko * ldb + col0;
#pragma unroll
        for (int i = 0; i < 2; i++) {
            int ff = tid + i * 256;
            int r = ff >> 5, c4 = (ff & 31) * 4;
            cp16(bB + (st * BSZ + r * 136 + c4) * 4, Bg + (size_t)r * ldb + c4);
        }
        CP_COMMIT();
    };

    const int nIter = K / 16;
    issue(0, 0);

    for (int it = 0; it < nIter; it++) {
        __syncthreads();
        if (it + 1 < nIter) { issue((it + 1) * 16, (it + 1) & 1); CP_WAIT1(); }
        else                { CP_WAIT0(); }
        __syncthreads();

        const float* cA = sA + (it & 1) * ASZ;
        const float* cB = sB + (it & 1) * BSZ;

#pragma unroll
        for (int kk = 0; kk < 16; kk += 8) {
            unsigned a[4][4], b[4][2];
#pragma unroll
            for (int mt = 0; mt < 4; mt++) {
                int rl = (wm * 64 + mt * 16 + g) * 20;
                int rh = rl + 8 * 20;
                a[mt][0] = FU(cA[rl + kk + t]);
                a[mt][1] = FU(cA[rh + kk + t]);
                a[mt][2] = FU(cA[rl + kk + t + 4]);
                a[mt][3] = FU(cA[rh + kk + t + 4]);
            }
#pragma unroll
            for (int nt = 0; nt < 4; nt++) {
                int cc = wn * 32 + nt * 8 + g;
                b[nt][0] = FU(cB[(kk + t) * 136 + cc]);
                b[nt][1] = FU(cB[(kk + t + 4) * 136 + cc]);
            }
#pragma unroll
            for (int mt = 0; mt < 4; mt++)
#pragma unroll
                for (int nt = 0; nt < 4; nt++)
                    mma8(c[mt * 4 + nt][0], c[mt * 4 + nt][1],
                         c[mt * 4 + nt][2], c[mt * 4 + nt][3],
                         a[mt][0], a[mt][1], a[mt][2], a[mt][3],
                         b[nt][0], b[nt][1]);
        }
    }
}

// ---------------------------------------------------------------------------
// Kernel 1: merged projections (blocks [0,256): QV; [256,384): K)
// Q/K written as fp16 [b,h,n,d]; V written fp16 TRANSPOSED [b,h,d,m].
// ---------------------------------------------------------------------------
__global__ void __launch_bounds__(256, 2) proj_kernel() {
    __shared__ float sA[2 * ASZ];
    __shared__ float sB[2 * BSZ];
    float c[16][4] = {};

    const int bid = blockIdx.x;
    const bool isQV = (bid < 256);
    int row0, col0;
    if (isQV) { col0 = (bid & 7) * 128;         row0 = (bid >> 3) * 128; }
    else      { col0 = ((bid - 256) & 3) * 128; row0 = ((bid - 256) >> 2) * 128; }

    if (isQV) gemm128_pipe(c_x,  DIMq, c_wqv, 2 * INNERq, row0, col0, DIMq, c, sA, sB);
    else      gemm128_pipe(c_x1, DIMq, c_wk,  INNERq,     row0, col0, DIMq, c, sA, sB);

    const int tid  = threadIdx.x;
    const int lane = tid & 31;
    const int w    = tid >> 5;
    const int wm   = w >> 2, wn = w & 3;
    const int g    = lane >> 2, t = lane & 3;

#pragma unroll
    for (int mt = 0; mt < 4; mt++) {
#pragma unroll
        for (int nt = 0; nt < 4; nt++) {
            int r  = row0 + wm * 64 + mt * 16 + g;
            int cc = col0 + wn * 32 + nt * 8 + 2 * t;
            int b  = r >> 11, n = r & 2047;
            float* p = &c[mt * 4 + nt][0];
            if (isQV && cc >= INNERq) {
                // V transposed fp16: [b,h,d,m]
                int colq = cc - INNERq;
                int h = colq >> 6, d = colq & 63;
                size_t vb = ((size_t)((b * Hq + h)) * DHq + d) * Mq + n;
                g_Vt[vb]          = __float2half_rn(p[0]);
                g_Vt[vb + Mq]     = __float2half_rn(p[1]);
                g_Vt[vb + 8]      = __float2half_rn(p[2]);
                g_Vt[vb + Mq + 8] = __float2half_rn(p[3]);
            } else {
                __half* dst = isQV ? g_Qh : g_Kh;
                int h = cc >> 6, d = cc & 63;
                size_t base = (((size_t)(b * Hq + h)) * Nq + n) * DHq + d;
                *(__half2*)&dst[base]           = __floats2half2_rn(p[0], p[1]);
                *(__half2*)&dst[base + 8 * DHq] = __floats2half2_rn(p[2], p[3]);
            }
        }
    }
}

// ---------------------------------------------------------------------------
// Kernel 2: flash attention, fp16 mma m16n8k16, deferred-PV pipeline.
// 64-row Q tiles, 4 warps x 16 rows, 3 blocks/SM (55.3KB smem).
// Smem halves (stride 72): P0@0, P1@4608 | K0@9216, K1@13824 | V0@18432,
// V1@23040.  Q staged in P0 (frags to regs), V tiles are [d][m].
// ---------------------------------------------------------------------------
#define HS   72
#define PH0  0
#define PH1  4608
#define KH0  9216
#define KH1  13824
#define VH0  18432
#define VH1  23040
#define ATTN_SMEM_BYTES (27648 * 2)   // 55,296 B

__global__ void __launch_bounds__(128, 3) attn_kernel(const float* __restrict__ attn_mat,
                                                      const float* __restrict__ dots_para,
                                                      const float* __restrict__ mat_para) {
    extern __shared__ __half hsm[];
    const int tid  = threadIdx.x;
    const int lane = tid & 31;
    const int w    = tid >> 5;
    const int g    = lane >> 2;
    const int t    = lane & 3;
    const int b    = blockIdx.z;
    const int h    = blockIdx.y;
    const int n0   = blockIdx.x * 64;
    const size_t bh = (size_t)(b * Hq + h);

    const float dp = __ldg(dots_para) * 0.125f;
    const float mp = __ldg(mat_para);

    const unsigned smB = (unsigned)__cvta_generic_to_shared(hsm);

    // Loaders: 64x64-half tiles, dst stride HS halves. 512 halves/op-row.
    auto ldK = [&](int ch) {     // K(ch) [m][d] -> K[ch&1]
        const __half* Kg = g_Kh + (bh * Mq + ch * 64) * DHq;
        unsigned dst = (ch & 1) ? KH1 : KH0;
#pragma unroll
        for (int i = 0; i < 4; i++) {
            int idx = tid + i * 128;
            int r = idx >> 3, c = idx & 7;
            cp16(smB + (dst + r * HS + c * 8) * 2, Kg + r * 64 + c * 8);
        }
    };
    auto ldV = [&](int ch) {     // V(ch) [d][m] -> V[ch&1]
        const __half* Vg = g_Vt + bh * DHq * (size_t)Mq + ch * 64;
        unsigned dst = (ch & 1) ? VH1 : VH0;
#pragma unroll
        for (int i = 0; i < 4; i++) {
            int idx = tid + i * 128;
            int r = idx >> 3, c = idx & 7;
            cp16(smB + (dst + r * HS + c * 8) * 2, Vg + (size_t)r * Mq + c * 8);
        }
    };

    // Prologue: Q -> P0 staging, K(0) | V(0)
    {
        const __half* Qg = g_Qh + (bh * Nq + n0) * DHq;
#pragma unroll
        for (int i = 0; i < 4; i++) {
            int idx = tid + i * 128;
            int r = idx >> 3, c = idx & 7;
            cp16(smB + (r * HS + c * 8) * 2, Qg + r * 64 + c * 8);
        }
        ldK(0);
        CP_COMMIT();
        ldV(0);
        CP_COMMIT();
        CP_WAIT0();
        __syncthreads();
    }

    // Q fragments (warp-private rows w*16+g, +8) from staging
    const int rl = (w * 16 + g) * HS;
    const int rh = rl + 8 * HS;
    unsigned qa[4][4];
#pragma unroll
    for (int j = 0; j < 4; j++) {
        qa[j][0] = *(const unsigned*)&hsm[rl + j * 16 + 2 * t];
        qa[j][1] = *(const unsigned*)&hsm[rh + j * 16 + 2 * t];
        qa[j][2] = *(const unsigned*)&hsm[rl + j * 16 + 8 + 2 * t];
        qa[j][3] = *(const unsigned*)&hsm[rh + j * 16 + 8 + 2 * t];
    }

    const float* AmBase = attn_mat + (bh * Nq + (n0 + w * 16 + g)) * (size_t)Mq;
    float o[8][4] = {};
    float rs0 = 0.0f, rs1 = 0.0f;

    // ---- Peeled chunk 0: S(0) + exp + store P(0) ----
    {
        ldK(1); CP_COMMIT();
        const float* Am = AmBase;
        float2 alo[8], ahi[8];
#pragma unroll
        for (int nt = 0; nt < 8; nt++) {
            alo[nt] = __ldg((const float2*)&Am[nt * 8 + 2 * t]);
            ahi[nt] = __ldg((const float2*)&Am[(size_t)8 * Mq + nt * 8 + 2 * t]);
        }
        const __half* Kb = hsm + KH0;
        float s[8][4] = {};
#pragma unroll
        for (int j = 0; j < 4; j++) {
#pragma unroll
            for (int nt = 0; nt < 8; nt++) {
                int cb = (nt * 8 + g) * HS + j * 16 + 2 * t;
                mma16(s[nt][0], s[nt][1], s[nt][2], s[nt][3],
                      qa[j][0], qa[j][1], qa[j][2], qa[j][3],
                      *(const unsigned*)&Kb[cb], *(const unsigned*)&Kb[cb + 8]);
            }
        }
        __half* Pc = hsm + PH0;
#pragma unroll
        for (int nt = 0; nt < 8; nt++) {
            float e0 = __expf(fmaf(s[nt][0], dp, mp * alo[nt].x));
            float e1 = __expf(fmaf(s[nt][1], dp, mp * alo[nt].y));
            float e2 = __expf(fmaf(s[nt][2], dp, mp * ahi[nt].x));
            float e3 = __expf(fmaf(s[nt][3], dp, mp * ahi[nt].y));
            rs0 += e0 + e1; rs1 += e2 + e3;
            *(__half2*)&Pc[rl + nt * 8 + 2 * t] = __floats2half2_rn(e0, e1);
            *(__half2*)&Pc[rh + nt * 8 + 2 * t] = __floats2half2_rn(e2, e3);
        }
        __syncthreads();
        ldV(1); CP_COMMIT();
    }

    // ---- Main loop: chunk ch does S(ch) + PV(ch-1) fused ----
    for (int ch = 1; ch < 32; ch++) {
        CP_WAIT1();          // K(ch) landed
        __syncthreads();
        if (ch < 31) { ldK(ch + 1); CP_COMMIT(); }

        const float* Am = AmBase + ch * 64;
        float2 alo[8], ahi[8];
#pragma unroll
        for (int nt = 0; nt < 8; nt++) {
            alo[nt] = __ldg((const float2*)&Am[nt * 8 + 2 * t]);
            ahi[nt] = __ldg((const float2*)&Am[(size_t)8 * Mq + nt * 8 + 2 * t]);
        }

        const __half* Kb = hsm + ((ch & 1) ? KH1 : KH0);
        const __half* Vb = hsm + (((ch - 1) & 1) ? VH1 : VH0);
        const __half* Pp = hsm + (((ch - 1) & 1) ? PH1 : PH0);
        __half* Pc = hsm + ((ch & 1) ? PH1 : PH0);

        float s[8][4] = {};
#pragma unroll
        for (int j = 0; j < 4; j++) {
            unsigned pa0 = *(const unsigned*)&Pp[rl + j * 16 + 2 * t];
            unsigned pa1 = *(const unsigned*)&Pp[rh + j * 16 + 2 * t];
            unsigned pa2 = *(const unsigned*)&Pp[rl + j * 16 + 8 + 2 * t];
            unsigned pa3 = *(const unsigned*)&Pp[rh + j * 16 + 8 + 2 * t];
#pragma unroll
            for (int nt = 0; nt < 8; nt++) {
                int cb = (nt * 8 + g) * HS + j * 16 + 2 * t;
                mma16(s[nt][0], s[nt][1], s[nt][2], s[nt][3],
                      qa[j][0], qa[j][1], qa[j][2], qa[j][3],
                      *(const unsigned*)&Kb[cb], *(const unsigned*)&Kb[cb + 8]);
                mma16(o[nt][0], o[nt][1], o[nt][2], o[nt][3],
                      pa0, pa1, pa2, pa3,
                      *(const unsigned*)&Vb[cb], *(const unsigned*)&Vb[cb + 8]);
            }
        }

        // softmax (no max; logits bounded) + store P(ch)
#pragma unroll
        for (int nt = 0; nt < 8; nt++) {
            float e0 = __expf(fmaf(s[nt][0], dp, mp * alo[nt].x));
            float e1 = __expf(fmaf(s[nt][1], dp, mp * alo[nt].y));
            float e2 = __expf(fmaf(s[nt][2], dp, mp * ahi[nt].x));
            float e3 = __expf(fmaf(s[nt][3], dp, mp * ahi[nt].y));
            rs0 += e0 + e1; rs1 += e2 + e3;
            *(__half2*)&Pc[rl + nt * 8 + 2 * t] = __floats2half2_rn(e0, e1);
            *(__half2*)&Pc[rh + nt * 8 + 2 * t] = __floats2half2_rn(e2, e3);
        }

        __syncthreads();
        if (ch < 31) { ldV(ch + 1); CP_COMMIT(); }
    }

    // ---- Final PV(31) ----
    CP_WAIT0();
    __syncthreads();
    {
        const __half* Vb = hsm + VH1;   // V[1]
        const __half* Pp = hsm + PH1;   // P[1]
#pragma unroll
        for (int j = 0; j < 4; j++) {
            unsigned pa0 = *(const unsigned*)&Pp[rl + j * 16 + 2 * t];
            unsigned pa1 = *(const unsigned*)&Pp[rh + j * 16 + 2 * t];
            unsigned pa2 = *(const unsigned*)&Pp[rl + j * 16 + 8 + 2 * t];
            unsigned pa3 = *(const unsigned*)&Pp[rh + j * 16 + 8 + 2 * t];
#pragma unroll
            for (int nt = 0; nt < 8; nt++) {
                int cb = (nt * 8 + g) * HS + j * 16 + 2 * t;
                mma16(o[nt][0], o[nt][1], o[nt][2], o[nt][3],
                      pa0, pa1, pa2, pa3,
                      *(const unsigned*)&Vb[cb], *(const unsigned*)&Vb[cb + 8]);
            }
        }
    }

    // ---- Epilogue ----
    rs0 += __shfl_xor_sync(0xffffffffu, rs0, 1);
    rs0 += __shfl_xor_sync(0xffffffffu, rs0, 2);
    rs1 += __shfl_xor_sync(0xffffffffu, rs1, 1);
    rs1 += __shfl_xor_sync(0xffffffffu, rs1, 2);
    float inv0 = 1.0f / rs0, inv1 = 1.0f / rs1;

    float* Og = g_O + ((size_t)b * Nq + n0 + w * 16 + g) * INNERq + h * DHq;
#pragma unroll
    for (int nt = 0; nt < 8; nt++) {
        *(float2*)&Og[nt * 8 + 2 * t] =
            make_float2(tf32r(o[nt][0] * inv0), tf32r(o[nt][1] * inv0));
        *(float2*)&Og[(size_t)8 * INNERq + nt * 8 + 2 * t] =
            make_float2(tf32r(o[nt][2] * inv1), tf32r(o[nt][3] * inv1));
    }
}

// ---------------------------------------------------------------------------
// Kernel 3: output projection (tf32 path, unchanged)
// ---------------------------------------------------------------------------
__global__ void __launch_bounds__(256, 2) out_proj_kernel(const float* __restrict__ bout,
                                                          float* __restrict__ out) {
    __shared__ float sA[2 * ASZ];
    __shared__ float sB[2 * BSZ];
    float c[16][4] = {};
    const int row0 = blockIdx.y * 128;
    const int col0 = blockIdx.x * 128;
    gemm128_pipe(g_O, INNERq, c_wo, DIMq, row0, col0, INNERq, c, sA, sB);

    const int tid  = threadIdx.x;
    const int lane = tid & 31;
    const int w    = tid >> 5;
    const int wm   = w >> 2, wn = w & 3;
    const int g    = lane >> 2, t = lane & 3;

#pragma unroll
    for (int mt = 0; mt < 4; mt++) {
#pragma unroll
        for (int nt = 0; nt < 4; nt++) {
            int r  = row0 + wm * 64 + mt * 16 + g;
            int cc = col0 + wn * 32 + nt * 8 + 2 * t;
            float2 bb = *(const float2*)&bout[cc];
            *(float2*)&out[(size_t)r * DIMq + cc] =
                make_float2(c[mt * 4 + nt][0] + bb.x, c[mt * 4 + nt][1] + bb.y);
            *(float2*)&out[(size_t)(r + 8) * DIMq + cc] =
                make_float2(c[mt * 4 + nt][2] + bb.x, c[mt * 4 + nt][3] + bb.y);
        }
    }
}

// ---------------------------------------------------------------------------
extern "C" void kernel_launch(void* const* d_in, const int* in_sizes, int n_in,
                              void* d_out, int out_size) {
    const float* x    = (const float*)d_in[0];
    const float* x1   = (const float*)d_in[1];
    const float* am   = (const float*)d_in[2];
    const float* dp   = (const float*)d_in[3];
    const float* mp   = (const float*)d_in[4];
    const float* Wqv  = (const float*)d_in[5];
    const float* Wk   = (const float*)d_in[6];
    const float* Wout = (const float*)d_in[7];
    const float* bout = (const float*)d_in[8];
    float* out = (float*)d_out;

    cudaFuncSetAttribute(attn_kernel, cudaFuncAttributeMaxDynamicSharedMemorySize,
                         ATTN_SMEM_BYTES);

    prep_kernel<<<(F4_TOT + 255) / 256, 256>>>(x, x1, Wqv, Wk, Wout);
    proj_kernel<<<384, 256>>>();
    attn_kernel<<<dim3(Nq / 64, Hq, Bq), 128, ATTN_SMEM_BYTES>>>(am, dp, mp);
    out_proj_kernel<<<dim3(DIMq / 128, 4096 / 128), 256>>>(bout, out);
}

// round 15
// speedup vs baseline: 1.5948x; 1.1112x over previous
#include <cuda_runtime.h>
#include <cuda_fp16.h>
#include <math.h>
#include <cstdint>

// Problem constants
#define Bq   2
#define Hq   8
#define Nq   2048
#define Mq   2048
#define DIMq 512
#define DHq  64
#define INNERq 512   // Hq*DHq

// Device scratch (no cudaMalloc allowed)
__device__ __half g_Qh[Bq * Hq * Nq * DHq];    // [b,h,n,d] fp16
__device__ __half g_Kh[Bq * Hq * Mq * DHq];    // [b,h,m,d] fp16
__device__ __half g_Vt[Bq * Hq * DHq * Mq];    // [b,h,d,m] fp16 TRANSPOSED
__device__ __half g_Of[Bq * Nq * INNERq];      // [b,n,h*d] fp16 (attn out)
// fp16 copies of projection inputs (weights pre-transposed: [n][k])
__device__ __half c_xh [Bq * Nq * DIMq];
__device__ __half c_x1h[Bq * Mq * DIMq];
__device__ __half w_qvT[2 * INNERq * DIMq];    // [1024][512]
__device__ __half w_kT [INNERq * DIMq];        // [512][512]
__device__ __half w_oT [DIMq * INNERq];        // [512][512]

// ---------------------------------------------------------------------------
__device__ __forceinline__ void mma16(float& c0, float& c1, float& c2, float& c3,
                                      unsigned a0, unsigned a1, unsigned a2, unsigned a3,
                                      unsigned b0, unsigned b1) {
    asm volatile(
        "mma.sync.aligned.m16n8k16.row.col.f32.f16.f16.f32 "
        "{%0,%1,%2,%3}, {%4,%5,%6,%7}, {%8,%9}, {%0,%1,%2,%3};\n"
        : "+f"(c0), "+f"(c1), "+f"(c2), "+f"(c3)
        : "r"(a0), "r"(a1), "r"(a2), "r"(a3), "r"(b0), "r"(b1));
}

__device__ __forceinline__ void cp16(unsigned dst, const void* src) {
    asm volatile("cp.async.cg.shared.global [%0], [%1], 16;\n" :: "r"(dst), "l"(src));
}
#define CP_COMMIT() asm volatile("cp.async.commit_group;\n")
#define CP_WAIT0()  asm volatile("cp.async.wait_group 0;\n")
#define CP_WAIT1()  asm volatile("cp.async.wait_group 1;\n")

// ---------------------------------------------------------------------------
// Kernel 0: convert inputs to fp16; transpose weights to [n][k].
// Items: x 524288 float4s, x1 524288 float4s, wqv^T 524288 elems,
// wk^T 262144 elems, wo^T 262144 elems => total 2,097,152 items.
// ---------------------------------------------------------------------------
#define IT_X   524288
#define IT_X1  524288
#define IT_WQV 524288
#define IT_WK  262144
#define IT_WO  262144
#define IT_TOT (IT_X + IT_X1 + IT_WQV + IT_WK + IT_WO)

__global__ void __launch_bounds__(256) prep_kernel(const float* __restrict__ x,
                                                   const float* __restrict__ x1,
                                                   const float* __restrict__ wqv,
                                                   const float* __restrict__ wk,
                                                   const float* __restrict__ wo) {
    int i = blockIdx.x * 256 + threadIdx.x;
    if (i >= IT_TOT) return;
    if (i < IT_X + IT_X1) {
        const float* src = (i < IT_X) ? x : x1;
        __half* dst = (i < IT_X) ? c_xh : c_x1h;
        int off = (i < IT_X) ? i : i - IT_X;
        float4 v = *(const float4*)&src[4 * (size_t)off];
        __half2 lo = __floats2half2_rn(v.x, v.y);
        __half2 hi = __floats2half2_rn(v.z, v.w);
        *(__half2*)&dst[4 * (size_t)off]     = lo;
        *(__half2*)&dst[4 * (size_t)off + 2] = hi;
        return;
    }
    i -= IT_X + IT_X1;
    if (i < IT_WQV) {
        int k = i >> 10, n = i & 1023;
        w_qvT[(size_t)n * DIMq + k] = __float2half_rn(wqv[i]);
        return;
    }
    i -= IT_WQV;
    if (i < IT_WK) {
        int k = i >> 9, n = i & 511;
        w_kT[(size_t)n * DIMq + k] = __float2half_rn(wk[i]);
        return;
    }
    i -= IT_WK;
    {
        int k = i >> 9, n = i & 511;
        w_oT[(size_t)n * INNERq + k] = __float2half_rn(wo[i]);
    }
}

// ---------------------------------------------------------------------------
// 128x128 fp16 GEMM core (mma.sync m16n8k16), cp.async 2-stage, K-chunk 32.
// A [rows][k] fp16 row-major; BT [n][k] fp16 (pre-transposed). K = 512.
// sA/sB: [2][128][40] halves. Fragment word addrs: 20g+t (conflict-free).
// ---------------------------------------------------------------------------
#define SAH  40
#define ASZH (128 * SAH)

__device__ __forceinline__ void gemm128_f16(const __half* __restrict__ A, int lda,
                                            const __half* __restrict__ BT, int ldb,
                                            int row0, int col0,
                                            float c[16][4],
                                            __half* sA, __half* sB) {
    const int tid  = threadIdx.x;
    const int lane = tid & 31;
    const int w    = tid >> 5;
    const int wm   = w >> 2;
    const int wn   = w & 3;
    const int g    = lane >> 2;
    const int t    = lane & 3;

    const unsigned aB = (unsigned)__cvta_generic_to_shared(sA);
    const unsigned bB = (unsigned)__cvta_generic_to_shared(sB);

    auto issue = [&](int ko, int st) {
        const __half* Ag = A + (size_t)row0 * lda + ko;
#pragma unroll
        for (int i = 0; i < 2; i++) {
            int ff = tid + i * 256;          // 512 ops: 128 rows x 4
            int r = ff >> 2, c8 = (ff & 3) * 8;
            cp16(aB + (st * ASZH + r * SAH + c8) * 2, Ag + (size_t)r * lda + c8);
        }
        const __half* Bg = BT + (size_t)col0 * ldb + ko;
#pragma unroll
        for (int i = 0; i < 2; i++) {
            int ff = tid + i * 256;
            int r = ff >> 2, c8 = (ff & 3) * 8;
            cp16(bB + (st * ASZH + r * SAH + c8) * 2, Bg + (size_t)r * ldb + c8);
        }
        CP_COMMIT();
    };

    const int nIter = DIMq / 32;   // K=512 -> 16
    issue(0, 0);

    for (int it = 0; it < nIter; it++) {
        __syncthreads();
        if (it + 1 < nIter) { issue((it + 1) * 32, (it + 1) & 1); CP_WAIT1(); }
        else                { CP_WAIT0(); }
        __syncthreads();

        const __half* cA = sA + (it & 1) * ASZH;
        const __half* cB = sB + (it & 1) * ASZH;

#pragma unroll
        for (int j = 0; j < 2; j++) {        // two k16 steps
            unsigned a[4][4], bfr[4][2];
#pragma unroll
            for (int mt = 0; mt < 4; mt++) {
                int rl = (wm * 64 + mt * 16 + g) * SAH + j * 16 + 2 * t;
                int rh = rl + 8 * SAH;
                a[mt][0] = *(const unsigned*)&cA[rl];
                a[mt][1] = *(const unsigned*)&cA[rh];
                a[mt][2] = *(const unsigned*)&cA[rl + 8];
                a[mt][3] = *(const unsigned*)&cA[rh + 8];
            }
#pragma unroll
            for (int nt = 0; nt < 4; nt++) {
                int cb = (wn * 32 + nt * 8 + g) * SAH + j * 16 + 2 * t;
                bfr[nt][0] = *(const unsigned*)&cB[cb];
                bfr[nt][1] = *(const unsigned*)&cB[cb + 8];
            }
#pragma unroll
            for (int mt = 0; mt < 4; mt++)
#pragma unroll
                for (int nt = 0; nt < 4; nt++)
                    mma16(c[mt * 4 + nt][0], c[mt * 4 + nt][1],
                          c[mt * 4 + nt][2], c[mt * 4 + nt][3],
                          a[mt][0], a[mt][1], a[mt][2], a[mt][3],
                          bfr[nt][0], bfr[nt][1]);
        }
    }
}

// ---------------------------------------------------------------------------
// Kernel 1: merged projections (blocks [0,256): QV; [256,384): K)
// Q/K written fp16 [b,h,n,d]; V written fp16 TRANSPOSED [b,h,d,m].
// ---------------------------------------------------------------------------
__global__ void __launch_bounds__(256, 2) proj_kernel() {
    __shared__ __half sA[2 * ASZH];
    __shared__ __half sB[2 * ASZH];
    float c[16][4] = {};

    const int bid = blockIdx.x;
    const bool isQV = (bid < 256);
    int row0, col0;
    if (isQV) { col0 = (bid & 7) * 128;         row0 = (bid >> 3) * 128; }
    else      { col0 = ((bid - 256) & 3) * 128; row0 = ((bid - 256) >> 2) * 128; }

    if (isQV) gemm128_f16(c_xh,  DIMq, w_qvT, DIMq, row0, col0, c, sA, sB);
    else      gemm128_f16(c_x1h, DIMq, w_kT,  DIMq, row0, col0, c, sA, sB);

    const int tid  = threadIdx.x;
    const int lane = tid & 31;
    const int w    = tid >> 5;
    const int wm   = w >> 2, wn = w & 3;
    const int g    = lane >> 2, t = lane & 3;

#pragma unroll
    for (int mt = 0; mt < 4; mt++) {
#pragma unroll
        for (int nt = 0; nt < 4; nt++) {
            int r  = row0 + wm * 64 + mt * 16 + g;
            int cc = col0 + wn * 32 + nt * 8 + 2 * t;
            int b  = r >> 11, n = r & 2047;
            float* p = &c[mt * 4 + nt][0];
            if (isQV && cc >= INNERq) {
                // V transposed fp16: [b,h,d,m]
                int colq = cc - INNERq;
                int h = colq >> 6, d = colq & 63;
                size_t vb = ((size_t)((b * Hq + h)) * DHq + d) * Mq + n;
                g_Vt[vb]          = __float2half_rn(p[0]);
                g_Vt[vb + Mq]     = __float2half_rn(p[1]);
                g_Vt[vb + 8]      = __float2half_rn(p[2]);
                g_Vt[vb + Mq + 8] = __float2half_rn(p[3]);
            } else {
                __half* dst = isQV ? g_Qh : g_Kh;
                int h = cc >> 6, d = cc & 63;
                size_t base = (((size_t)(b * Hq + h)) * Nq + n) * DHq + d;
                *(__half2*)&dst[base]           = __floats2half2_rn(p[0], p[1]);
                *(__half2*)&dst[base + 8 * DHq] = __floats2half2_rn(p[2], p[3]);
            }
        }
    }
}

// ---------------------------------------------------------------------------
// Kernel 2: flash attention, fp16 mma m16n8k16, deferred-PV pipeline.
// 64-row Q tiles, 4 warps x 16 rows, 3 blocks/SM (55.3KB smem).
// ---------------------------------------------------------------------------
#define HS   72
#define PH0  0
#define PH1  4608
#define KH0  9216
#define KH1  13824
#define VH0  18432
#define VH1  23040
#define ATTN_SMEM_BYTES (27648 * 2)   // 55,296 B

__global__ void __launch_bounds__(128, 3) attn_kernel(const float* __restrict__ attn_mat,
                                                      const float* __restrict__ dots_para,
                                                      const float* __restrict__ mat_para) {
    extern __shared__ __half hsm[];
    const int tid  = threadIdx.x;
    const int lane = tid & 31;
    const int w    = tid >> 5;
    const int g    = lane >> 2;
    const int t    = lane & 3;
    const int b    = blockIdx.z;
    const int h    = blockIdx.y;
    const int n0   = blockIdx.x * 64;
    const size_t bh = (size_t)(b * Hq + h);

    const float dp = __ldg(dots_para) * 0.125f;
    const float mp = __ldg(mat_para);

    const unsigned smB = (unsigned)__cvta_generic_to_shared(hsm);

    auto ldK = [&](int ch) {     // K(ch) [m][d] -> K[ch&1]
        const __half* Kg = g_Kh + (bh * Mq + ch * 64) * DHq;
        unsigned dst = (ch & 1) ? KH1 : KH0;
#pragma unroll
        for (int i = 0; i < 4; i++) {
            int idx = tid + i * 128;
            int r = idx >> 3, c = idx & 7;
            cp16(smB + (dst + r * HS + c * 8) * 2, Kg + r * 64 + c * 8);
        }
    };
    auto ldV = [&](int ch) {     // V(ch) [d][m] -> V[ch&1]
        const __half* Vg = g_Vt + bh * DHq * (size_t)Mq + ch * 64;
        unsigned dst = (ch & 1) ? VH1 : VH0;
#pragma unroll
        for (int i = 0; i < 4; i++) {
            int idx = tid + i * 128;
            int r = idx >> 3, c = idx & 7;
            cp16(smB + (dst + r * HS + c * 8) * 2, Vg + (size_t)r * Mq + c * 8);
        }
    };

    // Prologue: Q -> P0 staging, K(0) | V(0)
    {
        const __half* Qg = g_Qh + (bh * Nq + n0) * DHq;
#pragma unroll
        for (int i = 0; i < 4; i++) {
            int idx = tid + i * 128;
            int r = idx >> 3, c = idx & 7;
            cp16(smB + (r * HS + c * 8) * 2, Qg + r * 64 + c * 8);
        }
        ldK(0);
        CP_COMMIT();
        ldV(0);
        CP_COMMIT();
        CP_WAIT0();
        __syncthreads();
    }

    const int rl = (w * 16 + g) * HS;
    const int rh = rl + 8 * HS;
    unsigned qa[4][4];
#pragma unroll
    for (int j = 0; j < 4; j++) {
        qa[j][0] = *(const unsigned*)&hsm[rl + j * 16 + 2 * t];
        qa[j][1] = *(const unsigned*)&hsm[rh + j * 16 + 2 * t];
        qa[j][2] = *(const unsigned*)&hsm[rl + j * 16 + 8 + 2 * t];
        qa[j][3] = *(const unsigned*)&hsm[rh + j * 16 + 8 + 2 * t];
    }

    const float* AmBase = attn_mat + (bh * Nq + (n0 + w * 16 + g)) * (size_t)Mq;
    float o[8][4] = {};
    float rs0 = 0.0f, rs1 = 0.0f;

    // ---- Peeled chunk 0 ----
    {
        ldK(1); CP_COMMIT();
        const float* Am = AmBase;
        float2 alo[8], ahi[8];
#pragma unroll
        for (int nt = 0; nt < 8; nt++) {
            alo[nt] = __ldg((const float2*)&Am[nt * 8 + 2 * t]);
            ahi[nt] = __ldg((const float2*)&Am[(size_t)8 * Mq + nt * 8 + 2 * t]);
        }
        const __half* Kb = hsm + KH0;
        float s[8][4] = {};
#pragma unroll
        for (int j = 0; j < 4; j++) {
#pragma unroll
            for (int nt = 0; nt < 8; nt++) {
                int cb = (nt * 8 + g) * HS + j * 16 + 2 * t;
                mma16(s[nt][0], s[nt][1], s[nt][2], s[nt][3],
                      qa[j][0], qa[j][1], qa[j][2], qa[j][3],
                      *(const unsigned*)&Kb[cb], *(const unsigned*)&Kb[cb + 8]);
            }
        }
        __half* Pc = hsm + PH0;
#pragma unroll
        for (int nt = 0; nt < 8; nt++) {
            float e0 = __expf(fmaf(s[nt][0], dp, mp * alo[nt].x));
            float e1 = __expf(fmaf(s[nt][1], dp, mp * alo[nt].y));
            float e2 = __expf(fmaf(s[nt][2], dp, mp * ahi[nt].x));
            float e3 = __expf(fmaf(s[nt][3], dp, mp * ahi[nt].y));
            rs0 += e0 + e1; rs1 += e2 + e3;
            *(__half2*)&Pc[rl + nt * 8 + 2 * t] = __floats2half2_rn(e0, e1);
            *(__half2*)&Pc[rh + nt * 8 + 2 * t] = __floats2half2_rn(e2, e3);
        }
        __syncthreads();
        ldV(1); CP_COMMIT();
    }

    // ---- Main loop ----
    for (int ch = 1; ch < 32; ch++) {
        CP_WAIT1();
        __syncthreads();
        if (ch < 31) { ldK(ch + 1); CP_COMMIT(); }

        const float* Am = AmBase + ch * 64;
        float2 alo[8], ahi[8];
#pragma unroll
        for (int nt = 0; nt < 8; nt++) {
            alo[nt] = __ldg((const float2*)&Am[nt * 8 + 2 * t]);
            ahi[nt] = __ldg((const float2*)&Am[(size_t)8 * Mq + nt * 8 + 2 * t]);
        }

        const __half* Kb = hsm + ((ch & 1) ? KH1 : KH0);
        const __half* Vb = hsm + (((ch - 1) & 1) ? VH1 : VH0);
        const __half* Pp = hsm + (((ch - 1) & 1) ? PH1 : PH0);
        __half* Pc = hsm + ((ch & 1) ? PH1 : PH0);

        float s[8][4] = {};
#pragma unroll
        for (int j = 0; j < 4; j++) {
            unsigned pa0 = *(const unsigned*)&Pp[rl + j * 16 + 2 * t];
            unsigned pa1 = *(const unsigned*)&Pp[rh + j * 16 + 2 * t];
            unsigned pa2 = *(const unsigned*)&Pp[rl + j * 16 + 8 + 2 * t];
            unsigned pa3 = *(const unsigned*)&Pp[rh + j * 16 + 8 + 2 * t];
#pragma unroll
            for (int nt = 0; nt < 8; nt++) {
                int cb = (nt * 8 + g) * HS + j * 16 + 2 * t;
                mma16(s[nt][0], s[nt][1], s[nt][2], s[nt][3],
                      qa[j][0], qa[j][1], qa[j][2], qa[j][3],
                      *(const unsigned*)&Kb[cb], *(const unsigned*)&Kb[cb + 8]);
                mma16(o[nt][0], o[nt][1], o[nt][2], o[nt][3],
                      pa0, pa1, pa2, pa3,
                      *(const unsigned*)&Vb[cb], *(const unsigned*)&Vb[cb + 8]);
            }
        }

#pragma unroll
        for (int nt = 0; nt < 8; nt++) {
            float e0 = __expf(fmaf(s[nt][0], dp, mp * alo[nt].x));
            float e1 = __expf(fmaf(s[nt][1], dp, mp * alo[nt].y));
            float e2 = __expf(fmaf(s[nt][2], dp, mp * ahi[nt].x));
            float e3 = __expf(fmaf(s[nt][3], dp, mp * ahi[nt].y));
            rs0 += e0 + e1; rs1 += e2 + e3;
            *(__half2*)&Pc[rl + nt * 8 + 2 * t] = __floats2half2_rn(e0, e1);
            *(__half2*)&Pc[rh + nt * 8 + 2 * t] = __floats2half2_rn(e2, e3);
        }

        __syncthreads();
        if (ch < 31) { ldV(ch + 1); CP_COMMIT(); }
    }

    // ---- Final PV(31) ----
    CP_WAIT0();
    __syncthreads();
    {
        const __half* Vb = hsm + VH1;
        const __half* Pp = hsm + PH1;
#pragma unroll
        for (int j = 0; j < 4; j++) {
            unsigned pa0 = *(const unsigned*)&Pp[rl + j * 16 + 2 * t];
            unsigned pa1 = *(const unsigned*)&Pp[rh + j * 16 + 2 * t];
            unsigned pa2 = *(const unsigned*)&Pp[rl + j * 16 + 8 + 2 * t];
            unsigned pa3 = *(const unsigned*)&Pp[rh + j * 16 + 8 + 2 * t];
#pragma unroll
            for (int nt = 0; nt < 8; nt++) {
                int cb = (nt * 8 + g) * HS + j * 16 + 2 * t;
                mma16(o[nt][0], o[nt][1], o[nt][2], o[nt][3],
                      pa0, pa1, pa2, pa3,
                      *(const unsigned*)&Vb[cb], *(const unsigned*)&Vb[cb + 8]);
            }
        }
    }

    // ---- Epilogue (fp16 O) ----
    rs0 += __shfl_xor_sync(0xffffffffu, rs0, 1);
    rs0 += __shfl_xor_sync(0xffffffffu, rs0, 2);
    rs1 += __shfl_xor_sync(0xffffffffu, rs1, 1);
    rs1 += __shfl_xor_sync(0xffffffffu, rs1, 2);
    float inv0 = 1.0f / rs0, inv1 = 1.0f / rs1;

    __half* Og = g_Of + ((size_t)b * Nq + n0 + w * 16 + g) * INNERq + h * DHq;
#pragma unroll
    for (int nt = 0; nt < 8; nt++) {
        *(__half2*)&Og[nt * 8 + 2 * t] =
            __floats2half2_rn(o[nt][0] * inv0, o[nt][1] * inv0);
        *(__half2*)&Og[(size_t)8 * INNERq + nt * 8 + 2 * t] =
            __floats2half2_rn(o[nt][2] * inv1, o[nt][3] * inv1);
    }
}

// ---------------------------------------------------------------------------
// Kernel 3: output projection (fp16 GEMM)
// ---------------------------------------------------------------------------
__global__ void __launch_bounds__(256, 2) out_proj_kernel(const float* __restrict__ bout,
                                                          float* __restrict__ out) {
    __shared__ __half sA[2 * ASZH];
    __shared__ __half sB[2 * ASZH];
    float c[16][4] = {};
    const int row0 = blockIdx.y * 128;
    const int col0 = blockIdx.x * 128;
    gemm128_f16(g_Of, INNERq, w_oT, INNERq, row0, col0, c, sA, sB);

    const int tid  = threadIdx.x;
    const int lane = tid & 31;
    const int w    = tid >> 5;
    const int wm   = w >> 2, wn = w & 3;
    const int g    = lane >> 2, t = lane & 3;

#pragma unroll
    for (int mt = 0; mt < 4; mt++) {
#pragma unroll
        for (int nt = 0; nt < 4; nt++) {
            int r  = row0 + wm * 64 + mt * 16 + g;
            int cc = col0 + wn * 32 + nt * 8 + 2 * t;
            float2 bb = *(const float2*)&bout[cc];
            *(float2*)&out[(size_t)r * DIMq + cc] =
                make_float2(c[mt * 4 + nt][0] + bb.x, c[mt * 4 + nt][1] + bb.y);
            *(float2*)&out[(size_t)(r + 8) * DIMq + cc] =
                make_float2(c[mt * 4 + nt][2] + bb.x, c[mt * 4 + nt][3] + bb.y);
        }
    }
}

// ---------------------------------------------------------------------------
extern "C" void kernel_launch(void* const* d_in, const int* in_sizes, int n_in,
                              void* d_out, int out_size) {
    const float* x    = (const float*)d_in[0];
    const float* x1   = (const float*)d_in[1];
    const float* am   = (const float*)d_in[2];
    const float* dp   = (const float*)d_in[3];
    const float* mp   = (const float*)d_in[4];
    const float* Wqv  = (const float*)d_in[5];
    const float* Wk   = (const float*)d_in[6];
    const float* Wout = (const float*)d_in[7];
    const float* bout = (const float*)d_in[8];
    float* out = (float*)d_out;

    cudaFuncSetAttribute(attn_kernel, cudaFuncAttributeMaxDynamicSharedMemorySize,
                         ATTN_SMEM_BYTES);

    prep_kernel<<<(IT_TOT + 255) / 256, 256>>>(x, x1, Wqv, Wk, Wout);
    proj_kernel<<<384, 256>>>();
    attn_kernel<<<dim3(Nq / 64, Hq, Bq), 128, ATTN_SMEM_BYTES>>>(am, dp, mp);
    out_proj_kernel<<<dim3(DIMq / 128, 4096 / 128), 256>>>(bout, out);
}